// round 1
// baseline (speedup 1.0000x reference)
#include <cuda_runtime.h>
#include <math.h>

#define Bsz 8
#define Sq  512
#define Dm  768
#define Hn  12
#define HDm 64
#define En  8
#define FFd 3072
#define TOK 4096
#define BHN 96

// ---------------- scratch (device globals; no allocations allowed) ----------
__device__ float g_h[TOK * Dm];
__device__ float g_qkv[TOK * 3 * Dm];
__device__ float g_scores[(size_t)BHN * Sq * Sq];
__device__ float g_o[TOK * Dm];
__device__ float g_h2[TOK * Dm];
__device__ float g_y1[(size_t)TOK * FFd];
__device__ int   g_routes[TOK];
__device__ int   g_cnt[En];
__device__ int   g_off[En];
__device__ int   g_cur[En];
__device__ int   g_sorted[TOK];

// ---------------- helpers ---------------------------------------------------
__device__ __forceinline__ float gelu_exact(float x) {
    return 0.5f * x * (1.0f + erff(x * 0.70710678118654752f));
}

// ---------------- reset counters --------------------------------------------
__global__ void reset_kernel() {
    int t = threadIdx.x;
    if (t < En) { g_cnt[t] = 0; g_cur[t] = 0; }
}

// ---------------- layernorm: one block (256 thr) per row of 768 -------------
__global__ void ln_kernel(const float* __restrict__ X,
                          const float* __restrict__ gam,
                          const float* __restrict__ bet,
                          float* __restrict__ Y) {
    int row = blockIdx.x;
    int tid = threadIdx.x;
    const float* x = X + (size_t)row * Dm;
    float v0 = x[tid], v1 = x[tid + 256], v2 = x[tid + 512];

    __shared__ float red[256];
    float s = v0 + v1 + v2;
    red[tid] = s; __syncthreads();
    #pragma unroll
    for (int st = 128; st > 0; st >>= 1) {
        if (tid < st) red[tid] += red[tid + st];
        __syncthreads();
    }
    float mu = red[0] / (float)Dm;
    __syncthreads();

    float d0 = v0 - mu, d1 = v1 - mu, d2 = v2 - mu;
    float q = d0 * d0 + d1 * d1 + d2 * d2;
    red[tid] = q; __syncthreads();
    #pragma unroll
    for (int st = 128; st > 0; st >>= 1) {
        if (tid < st) red[tid] += red[tid + st];
        __syncthreads();
    }
    float rstd = rsqrtf(red[0] / (float)Dm + 1e-5f);

    float* y = Y + (size_t)row * Dm;
    y[tid]       = d0 * rstd * gam[tid]       + bet[tid];
    y[tid + 256] = d1 * rstd * gam[tid + 256] + bet[tid + 256];
    y[tid + 512] = d2 * rstd * gam[tid + 512] + bet[tid + 512];
}

// ---------------- generic fp32 GEMM: C = A@B (+bias)(+resid) ----------------
// BM=BN=128, BK=16, 256 threads, 8x8 per thread. All dims divisible.
#define GBM 128
#define GBN 128
#define GBK 16
__global__ void gemm_kernel(const float* __restrict__ A,
                            const float* __restrict__ B,
                            float* __restrict__ C,
                            int M, int N, int K,
                            const float* __restrict__ bias,
                            const float* __restrict__ resid) {
    __shared__ float As[GBK][GBM];
    __shared__ float Bs[GBK][GBN];
    int tid = threadIdx.x;
    int n0 = blockIdx.x * GBN;
    int m0 = blockIdx.y * GBM;
    int tx = tid & 15, ty = tid >> 4;

    float acc[8][8];
    #pragma unroll
    for (int i = 0; i < 8; i++)
        #pragma unroll
        for (int j = 0; j < 8; j++) acc[i][j] = 0.f;

    for (int k0 = 0; k0 < K; k0 += GBK) {
        #pragma unroll
        for (int l = 0; l < 2; l++) {
            int idx = tid + l * 256;
            int r = idx >> 2;
            int c4 = (idx & 3) * 4;
            float4 v = *(const float4*)(A + (size_t)(m0 + r) * K + k0 + c4);
            As[c4 + 0][r] = v.x; As[c4 + 1][r] = v.y;
            As[c4 + 2][r] = v.z; As[c4 + 3][r] = v.w;
        }
        #pragma unroll
        for (int l = 0; l < 2; l++) {
            int idx = tid + l * 256;
            int r = idx >> 5;
            int c4 = (idx & 31) * 4;
            *(float4*)&Bs[r][c4] = *(const float4*)(B + (size_t)(k0 + r) * N + n0 + c4);
        }
        __syncthreads();
        #pragma unroll
        for (int k = 0; k < GBK; k++) {
            float4 a0 = *(float4*)&As[k][ty * 8];
            float4 a1 = *(float4*)&As[k][ty * 8 + 4];
            float4 b0 = *(float4*)&Bs[k][tx * 8];
            float4 b1 = *(float4*)&Bs[k][tx * 8 + 4];
            float ra[8] = {a0.x,a0.y,a0.z,a0.w,a1.x,a1.y,a1.z,a1.w};
            float rb[8] = {b0.x,b0.y,b0.z,b0.w,b1.x,b1.y,b1.z,b1.w};
            #pragma unroll
            for (int i = 0; i < 8; i++)
                #pragma unroll
                for (int j = 0; j < 8; j++)
                    acc[i][j] += ra[i] * rb[j];
        }
        __syncthreads();
    }
    #pragma unroll
    for (int i = 0; i < 8; i++) {
        int m = m0 + ty * 8 + i;
        #pragma unroll
        for (int j = 0; j < 8; j++) {
            int n = n0 + tx * 8 + j;
            float v = acc[i][j];
            if (bias)  v += bias[n];
            if (resid) v += resid[(size_t)m * N + n];
            C[(size_t)m * N + n] = v;
        }
    }
}

// ---------------- attention scores: S = scale * Q @ K^T ---------------------
__global__ void scores_kernel(const float* __restrict__ QKV,
                              float* __restrict__ S) {
    int bh = blockIdx.z;
    int b = bh / Hn, h = bh % Hn;
    int m0 = blockIdx.y * 64, n0 = blockIdx.x * 64;
    __shared__ float Qs[64][68];
    __shared__ float Ks[64][68];
    int tid = threadIdx.x;
    int tx = tid & 15, ty = tid >> 4;

    #pragma unroll
    for (int l = 0; l < 4; l++) {
        int idx = tid + l * 256;
        int r = idx >> 4;
        int c4 = (idx & 15) * 4;
        *(float4*)&Qs[r][c4] =
            *(const float4*)(QKV + (size_t)(b * Sq + m0 + r) * 2304 + h * HDm + c4);
        *(float4*)&Ks[r][c4] =
            *(const float4*)(QKV + (size_t)(b * Sq + n0 + r) * 2304 + Dm + h * HDm + c4);
    }
    __syncthreads();

    float acc[4][4];
    #pragma unroll
    for (int i = 0; i < 4; i++)
        #pragma unroll
        for (int j = 0; j < 4; j++) acc[i][j] = 0.f;

    #pragma unroll 8
    for (int c = 0; c < 64; c++) {
        float ra[4], rb[4];
        #pragma unroll
        for (int i = 0; i < 4; i++) ra[i] = Qs[ty * 4 + i][c];
        #pragma unroll
        for (int j = 0; j < 4; j++) rb[j] = Ks[tx * 4 + j][c];
        #pragma unroll
        for (int i = 0; i < 4; i++)
            #pragma unroll
            for (int j = 0; j < 4; j++)
                acc[i][j] += ra[i] * rb[j];
    }
    const float scale = 0.125f;  // 64^-0.5
    #pragma unroll
    for (int i = 0; i < 4; i++) {
        size_t rowp = ((size_t)bh * Sq + m0 + ty * 4 + i) * Sq + n0 + tx * 4;
        #pragma unroll
        for (int j = 0; j < 4; j++)
            S[rowp + j] = acc[i][j] * scale;
    }
}

// ---------------- row softmax over 512 --------------------------------------
__global__ void softmax_kernel(float* __restrict__ S) {
    size_t row = blockIdx.x;
    int tid = threadIdx.x;
    float* p = S + row * Sq;
    float v0 = p[tid], v1 = p[tid + 256];

    __shared__ float red[256];
    float m = fmaxf(v0, v1);
    red[tid] = m; __syncthreads();
    #pragma unroll
    for (int st = 128; st > 0; st >>= 1) {
        if (tid < st) red[tid] = fmaxf(red[tid], red[tid + st]);
        __syncthreads();
    }
    m = red[0]; __syncthreads();

    float e0 = __expf(v0 - m), e1 = __expf(v1 - m);
    red[tid] = e0 + e1; __syncthreads();
    #pragma unroll
    for (int st = 128; st > 0; st >>= 1) {
        if (tid < st) red[tid] += red[tid + st];
        __syncthreads();
    }
    float inv = 1.0f / red[0];
    p[tid] = e0 * inv;
    p[tid + 256] = e1 * inv;
}

// ---------------- O = P @ V --------------------------------------------------
__global__ void av_kernel(const float* __restrict__ S,
                          const float* __restrict__ QKV,
                          float* __restrict__ O) {
    int bh = blockIdx.y;
    int b = bh / Hn, h = bh % Hn;
    int m0 = blockIdx.x * 64;
    __shared__ float Ps[64][36];
    __shared__ float Vs[32][68];
    int tid = threadIdx.x;
    int tx = tid & 15, ty = tid >> 4;

    float acc[4][4];
    #pragma unroll
    for (int i = 0; i < 4; i++)
        #pragma unroll
        for (int j = 0; j < 4; j++) acc[i][j] = 0.f;

    for (int k0 = 0; k0 < Sq; k0 += 32) {
        #pragma unroll
        for (int l = 0; l < 2; l++) {
            int idx = tid + l * 256;
            int r = idx >> 3;
            int c4 = (idx & 7) * 4;
            *(float4*)&Ps[r][c4] =
                *(const float4*)(S + ((size_t)bh * Sq + m0 + r) * Sq + k0 + c4);
        }
        #pragma unroll
        for (int l = 0; l < 2; l++) {
            int idx = tid + l * 256;
            int r = idx >> 4;
            int c4 = (idx & 15) * 4;
            *(float4*)&Vs[r][c4] =
                *(const float4*)(QKV + (size_t)(b * Sq + k0 + r) * 2304 + 2 * Dm + h * HDm + c4);
        }
        __syncthreads();
        #pragma unroll 4
        for (int k = 0; k < 32; k++) {
            float ra[4], rb[4];
            #pragma unroll
            for (int i = 0; i < 4; i++) ra[i] = Ps[ty * 4 + i][k];
            #pragma unroll
            for (int j = 0; j < 4; j++) rb[j] = Vs[k][tx * 4 + j];
            #pragma unroll
            for (int i = 0; i < 4; i++)
                #pragma unroll
                for (int j = 0; j < 4; j++)
                    acc[i][j] += ra[i] * rb[j];
        }
        __syncthreads();
    }
    #pragma unroll
    for (int i = 0; i < 4; i++) {
        size_t rowp = (size_t)(b * Sq + m0 + ty * 4 + i) * Dm + h * HDm + tx * 4;
        #pragma unroll
        for (int j = 0; j < 4; j++)
            O[rowp + j] = acc[i][j];
    }
}

// ---------------- router: one warp per token ---------------------------------
__global__ void route_kernel(const float* __restrict__ H2,
                             const float* __restrict__ SW,
                             const float* __restrict__ SB) {
    int warp = (blockIdx.x * blockDim.x + threadIdx.x) >> 5;
    int lane = threadIdx.x & 31;
    if (warp >= TOK) return;
    const float* hrow = H2 + (size_t)warp * Dm;
    float acc[En];
    #pragma unroll
    for (int e = 0; e < En; e++) acc[e] = 0.f;
    for (int d = lane; d < Dm; d += 32) {
        float hv = hrow[d];
        const float* w = SW + d * En;
        #pragma unroll
        for (int e = 0; e < En; e++) acc[e] += hv * w[e];
    }
    #pragma unroll
    for (int e = 0; e < En; e++)
        #pragma unroll
        for (int o = 16; o; o >>= 1)
            acc[e] += __shfl_xor_sync(0xffffffffu, acc[e], o);
    if (lane == 0) {
        float best = acc[0] + SB[0];
        int be = 0;
        #pragma unroll
        for (int e = 1; e < En; e++) {
            float v = acc[e] + SB[e];
            if (v > best) { best = v; be = e; }
        }
        g_routes[warp] = be;
        atomicAdd(&g_cnt[be], 1);
    }
}

__global__ void offsets_kernel() {
    if (threadIdx.x == 0) {
        int acc = 0;
        for (int e = 0; e < En; e++) { g_off[e] = acc; acc += g_cnt[e]; }
    }
}

__global__ void scatter_kernel() {
    int t = blockIdx.x * blockDim.x + threadIdx.x;
    if (t >= TOK) return;
    int e = g_routes[t];
    int pos = atomicAdd(&g_cur[e], 1);
    g_sorted[g_off[e] + pos] = t;
}

// ---------------- MoE GEMM 1: Y1 = gelu(gather(H2) @ W1[e] + b1[e]) ----------
__global__ void moe_gemm1(const float* __restrict__ H2,
                          const float* __restrict__ W1,
                          const float* __restrict__ B1,
                          float* __restrict__ Y1) {
    int e = blockIdx.z;
    int cnt = g_cnt[e];
    int m0 = blockIdx.y * GBM;
    if (m0 >= cnt) return;
    int off = g_off[e];
    const float* B = W1 + (size_t)e * Dm * FFd;
    const int N = FFd, K = Dm;
    int n0 = blockIdx.x * GBN;

    __shared__ float As[GBK][GBM];
    __shared__ float Bs[GBK][GBN];
    __shared__ int toks[GBM];
    int tid = threadIdx.x;
    int tx = tid & 15, ty = tid >> 4;
    if (tid < GBM) {
        int m = m0 + tid;
        toks[tid] = (m < cnt) ? g_sorted[off + m] : -1;
    }
    __syncthreads();

    float acc[8][8];
    #pragma unroll
    for (int i = 0; i < 8; i++)
        #pragma unroll
        for (int j = 0; j < 8; j++) acc[i][j] = 0.f;

    for (int k0 = 0; k0 < K; k0 += GBK) {
        #pragma unroll
        for (int l = 0; l < 2; l++) {
            int idx = tid + l * 256;
            int r = idx >> 2;
            int c4 = (idx & 3) * 4;
            int tok = toks[r];
            float4 v = make_float4(0.f, 0.f, 0.f, 0.f);
            if (tok >= 0)
                v = *(const float4*)(H2 + (size_t)tok * Dm + k0 + c4);
            As[c4 + 0][r] = v.x; As[c4 + 1][r] = v.y;
            As[c4 + 2][r] = v.z; As[c4 + 3][r] = v.w;
        }
        #pragma unroll
        for (int l = 0; l < 2; l++) {
            int idx = tid + l * 256;
            int r = idx >> 5;
            int c4 = (idx & 31) * 4;
            *(float4*)&Bs[r][c4] = *(const float4*)(B + (size_t)(k0 + r) * N + n0 + c4);
        }
        __syncthreads();
        #pragma unroll
        for (int k = 0; k < GBK; k++) {
            float4 a0 = *(float4*)&As[k][ty * 8];
            float4 a1 = *(float4*)&As[k][ty * 8 + 4];
            float4 b0 = *(float4*)&Bs[k][tx * 8];
            float4 b1 = *(float4*)&Bs[k][tx * 8 + 4];
            float ra[8] = {a0.x,a0.y,a0.z,a0.w,a1.x,a1.y,a1.z,a1.w};
            float rb[8] = {b0.x,b0.y,b0.z,b0.w,b1.x,b1.y,b1.z,b1.w};
            #pragma unroll
            for (int i = 0; i < 8; i++)
                #pragma unroll
                for (int j = 0; j < 8; j++)
                    acc[i][j] += ra[i] * rb[j];
        }
        __syncthreads();
    }
    #pragma unroll
    for (int i = 0; i < 8; i++) {
        int m = m0 + ty * 8 + i;
        if (m >= cnt) continue;
        #pragma unroll
        for (int j = 0; j < 8; j++) {
            int n = n0 + tx * 8 + j;
            float v = acc[i][j] + B1[e * FFd + n];
            Y1[(size_t)(off + m) * FFd + n] = gelu_exact(v);
        }
    }
}

// ---------------- MoE GEMM 2: out[t] += gelu(Y1 @ W2[e] + b2[e]) -------------
__global__ void moe_gemm2(const float* __restrict__ Y1,
                          const float* __restrict__ W2,
                          const float* __restrict__ B2,
                          float* __restrict__ OUT) {
    int e = blockIdx.z;
    int cnt = g_cnt[e];
    int m0 = blockIdx.y * GBM;
    if (m0 >= cnt) return;
    int off = g_off[e];
    const float* B = W2 + (size_t)e * FFd * Dm;
    const int N = Dm, K = FFd;
    int n0 = blockIdx.x * GBN;

    __shared__ float As[GBK][GBM];
    __shared__ float Bs[GBK][GBN];
    __shared__ int toks[GBM];
    int tid = threadIdx.x;
    int tx = tid & 15, ty = tid >> 4;
    if (tid < GBM) {
        int m = m0 + tid;
        toks[tid] = (m < cnt) ? g_sorted[off + m] : -1;
    }
    __syncthreads();

    float acc[8][8];
    #pragma unroll
    for (int i = 0; i < 8; i++)
        #pragma unroll
        for (int j = 0; j < 8; j++) acc[i][j] = 0.f;

    for (int k0 = 0; k0 < K; k0 += GBK) {
        #pragma unroll
        for (int l = 0; l < 2; l++) {
            int idx = tid + l * 256;
            int r = idx >> 2;
            int c4 = (idx & 3) * 4;
            float4 v = make_float4(0.f, 0.f, 0.f, 0.f);
            if (m0 + r < cnt)
                v = *(const float4*)(Y1 + (size_t)(off + m0 + r) * FFd + k0 + c4);
            As[c4 + 0][r] = v.x; As[c4 + 1][r] = v.y;
            As[c4 + 2][r] = v.z; As[c4 + 3][r] = v.w;
        }
        #pragma unroll
        for (int l = 0; l < 2; l++) {
            int idx = tid + l * 256;
            int r = idx >> 5;
            int c4 = (idx & 31) * 4;
            *(float4*)&Bs[r][c4] = *(const float4*)(B + (size_t)(k0 + r) * N + n0 + c4);
        }
        __syncthreads();
        #pragma unroll
        for (int k = 0; k < GBK; k++) {
            float4 a0 = *(float4*)&As[k][ty * 8];
            float4 a1 = *(float4*)&As[k][ty * 8 + 4];
            float4 b0 = *(float4*)&Bs[k][tx * 8];
            float4 b1 = *(float4*)&Bs[k][tx * 8 + 4];
            float ra[8] = {a0.x,a0.y,a0.z,a0.w,a1.x,a1.y,a1.z,a1.w};
            float rb[8] = {b0.x,b0.y,b0.z,b0.w,b1.x,b1.y,b1.z,b1.w};
            #pragma unroll
            for (int i = 0; i < 8; i++)
                #pragma unroll
                for (int j = 0; j < 8; j++)
                    acc[i][j] += ra[i] * rb[j];
        }
        __syncthreads();
    }
    #pragma unroll
    for (int i = 0; i < 8; i++) {
        int m = m0 + ty * 8 + i;
        if (m >= cnt) continue;
        int t = toks[ty * 8 + i];
        #pragma unroll
        for (int j = 0; j < 8; j++) {
            int n = n0 + tx * 8 + j;
            float v = acc[i][j] + B2[e * Dm + n];
            OUT[(size_t)t * Dm + n] += gelu_exact(v);
        }
    }
}

// ---------------- launch ------------------------------------------------------
extern "C" void kernel_launch(void* const* d_in, const int* in_sizes, int n_in,
                              void* d_out, int out_size) {
    const float* x       = (const float*)d_in[0];
    // d_in[1] = indexes_list (unused by reference math)
    const float* ln1_g   = (const float*)d_in[2];
    const float* ln1_b   = (const float*)d_in[3];
    const float* qkv_w   = (const float*)d_in[4];
    const float* proj_w  = (const float*)d_in[5];
    const float* proj_b  = (const float*)d_in[6];
    const float* ln2_g   = (const float*)d_in[7];
    const float* ln2_b   = (const float*)d_in[8];
    const float* sw_w    = (const float*)d_in[9];
    const float* sw_b    = (const float*)d_in[10];
    const float* w1      = (const float*)d_in[11];
    const float* b1      = (const float*)d_in[12];
    const float* w2      = (const float*)d_in[13];
    const float* b2      = (const float*)d_in[14];
    float* out = (float*)d_out;

    float *gh, *gqkv, *gs, *go, *gh2, *gy1;
    cudaGetSymbolAddress((void**)&gh,   g_h);
    cudaGetSymbolAddress((void**)&gqkv, g_qkv);
    cudaGetSymbolAddress((void**)&gs,   g_scores);
    cudaGetSymbolAddress((void**)&go,   g_o);
    cudaGetSymbolAddress((void**)&gh2,  g_h2);
    cudaGetSymbolAddress((void**)&gy1,  g_y1);

    reset_kernel<<<1, 32>>>();

    // ln1
    ln_kernel<<<TOK, 256>>>(x, ln1_g, ln1_b, gh);

    // qkv = h @ qkv_w   [4096 x 2304]
    gemm_kernel<<<dim3(2304 / GBN, TOK / GBM), 256>>>(gh, qkv_w, gqkv,
                                                      TOK, 2304, Dm, nullptr, nullptr);
    // scores
    scores_kernel<<<dim3(Sq / 64, Sq / 64, BHN), 256>>>(gqkv, gs);
    // softmax
    softmax_kernel<<<BHN * Sq, 256>>>(gs);
    // o = P @ V
    av_kernel<<<dim3(Sq / 64, BHN), 256>>>(gs, gqkv, go);
    // xmid = x + o @ proj_w + proj_b   -> written into d_out
    gemm_kernel<<<dim3(Dm / GBN, TOK / GBM), 256>>>(go, proj_w, out,
                                                    TOK, Dm, Dm, proj_b, x);
    // ln2
    ln_kernel<<<TOK, 256>>>(out, ln2_g, ln2_b, gh2);
    // routing
    route_kernel<<<512, 256>>>(gh2, sw_w, sw_b);
    offsets_kernel<<<1, 32>>>();
    scatter_kernel<<<TOK / 256, 256>>>();
    // MoE expert GEMMs (grouped tokens); extra tiles exit early
    moe_gemm1<<<dim3(FFd / GBN, TOK / GBM, En), 256>>>(gh2, w1, b1, gy1);
    moe_gemm2<<<dim3(Dm / GBN, TOK / GBM, En), 256>>>(gy1, w2, b2, out);
}

// round 2
// speedup vs baseline: 2.3619x; 2.3619x over previous
#include <cuda_runtime.h>
#include <math.h>

#define Bsz 8
#define Sq  512
#define Dm  768
#define Hn  12
#define HDm 64
#define En  8
#define FFd 3072
#define TOK 4096
#define BHN 96

// ---------------- scratch (device globals; no allocations allowed) ----------
__device__ float g_h[TOK * Dm];
__device__ float g_qkv[TOK * 3 * Dm];
__device__ float g_scores[(size_t)BHN * Sq * Sq];
__device__ float g_o[TOK * Dm];
__device__ float g_h2[TOK * Dm];
__device__ float g_y1[(size_t)TOK * FFd];
__device__ int   g_routes[TOK];
__device__ int   g_cnt[En];
__device__ int   g_off[En];
__device__ int   g_cur[En];
__device__ int   g_sorted[TOK];

// ---------------- helpers ---------------------------------------------------
__device__ __forceinline__ float gelu_exact(float x) {
    return 0.5f * x * (1.0f + erff(x * 0.70710678118654752f));
}

__device__ __forceinline__ unsigned f2t(float f) {
    unsigned u;
    asm("cvt.rna.tf32.f32 %0, %1;" : "=r"(u) : "f"(f));
    return u;
}
__device__ __forceinline__ uint4 cvt4(float4 v) {
    return make_uint4(f2t(v.x), f2t(v.y), f2t(v.z), f2t(v.w));
}

__device__ __forceinline__ void mma_tf32(float c[4],
                                         unsigned a0, unsigned a1, unsigned a2, unsigned a3,
                                         unsigned b0, unsigned b1) {
    asm volatile(
        "mma.sync.aligned.m16n8k8.row.col.f32.tf32.tf32.f32 "
        "{%0,%1,%2,%3},{%4,%5,%6,%7},{%8,%9},{%0,%1,%2,%3};"
        : "+f"(c[0]), "+f"(c[1]), "+f"(c[2]), "+f"(c[3])
        : "r"(a0), "r"(a1), "r"(a2), "r"(a3), "r"(b0), "r"(b1));
}

// ---------------- reset counters --------------------------------------------
__global__ void reset_kernel() {
    int t = threadIdx.x;
    if (t < En) { g_cnt[t] = 0; g_cur[t] = 0; }
}

// ---------------- layernorm: one block (256 thr) per row of 768 -------------
__global__ void ln_kernel(const float* __restrict__ X,
                          const float* __restrict__ gam,
                          const float* __restrict__ bet,
                          float* __restrict__ Y) {
    int row = blockIdx.x;
    int tid = threadIdx.x;
    const float* x = X + (size_t)row * Dm;
    float v0 = x[tid], v1 = x[tid + 256], v2 = x[tid + 512];

    __shared__ float red[256];
    float s = v0 + v1 + v2;
    red[tid] = s; __syncthreads();
    #pragma unroll
    for (int st = 128; st > 0; st >>= 1) {
        if (tid < st) red[tid] += red[tid + st];
        __syncthreads();
    }
    float mu = red[0] / (float)Dm;
    __syncthreads();

    float d0 = v0 - mu, d1 = v1 - mu, d2 = v2 - mu;
    float q = d0 * d0 + d1 * d1 + d2 * d2;
    red[tid] = q; __syncthreads();
    #pragma unroll
    for (int st = 128; st > 0; st >>= 1) {
        if (tid < st) red[tid] += red[tid + st];
        __syncthreads();
    }
    float rstd = rsqrtf(red[0] / (float)Dm + 1e-5f);

    float* y = Y + (size_t)row * Dm;
    y[tid]       = d0 * rstd * gam[tid]       + bet[tid];
    y[tid + 256] = d1 * rstd * gam[tid + 256] + bet[tid + 256];
    y[tid + 512] = d2 * rstd * gam[tid + 512] + bet[tid + 512];
}

// =============================================================================
// Generic tf32 tensor-core GEMM: C = A@B (+bias)(+resid)
// BM=128, BN=128, BK=16, 256 threads = 8 warps (2x4), warp tile 64x32.
// As: row-major [m][k], stride 20 (20 mod 32 = 20, frag banks 20m+tg distinct).
// Bs: row-major [k][n], stride 136 (mod 32 = 8, frag banks 8k+gid distinct).
// =============================================================================
#define ASTR 20
#define BSTR 136

__global__ void gemm_tf32(const float* __restrict__ A, const float* __restrict__ B,
                          float* __restrict__ C, int M, int N, int K,
                          const float* __restrict__ bias,
                          const float* __restrict__ resid) {
    __shared__ unsigned As[128 * ASTR];
    __shared__ unsigned Bs[16 * BSTR];
    int tid = threadIdx.x;
    int warp = tid >> 5, lane = tid & 31;
    int gid = lane >> 2, tg = lane & 3;
    int wm = (warp >> 2) * 64, wn = (warp & 3) * 32;
    int m0 = blockIdx.y * 128, n0 = blockIdx.x * 128;

    float acc[4][4][4];
    #pragma unroll
    for (int i = 0; i < 4; i++)
        #pragma unroll
        for (int j = 0; j < 4; j++)
            #pragma unroll
            for (int q = 0; q < 4; q++) acc[i][j][q] = 0.f;

    for (int k0 = 0; k0 < K; k0 += 16) {
        #pragma unroll
        for (int l = 0; l < 2; l++) {
            int idx = tid + l * 256, r = idx >> 2, c4 = (idx & 3) * 4;
            float4 v = *(const float4*)(A + (size_t)(m0 + r) * K + k0 + c4);
            *(uint4*)&As[r * ASTR + c4] = cvt4(v);
        }
        #pragma unroll
        for (int l = 0; l < 2; l++) {
            int idx = tid + l * 256, r = idx >> 5, c4 = (idx & 31) * 4;
            float4 v = *(const float4*)(B + (size_t)(k0 + r) * N + n0 + c4);
            *(uint4*)&Bs[r * BSTR + c4] = cvt4(v);
        }
        __syncthreads();
        #pragma unroll
        for (int ks = 0; ks < 2; ks++) {
            int kb = ks * 8;
            unsigned af[4][4], bf[4][2];
            #pragma unroll
            for (int mt = 0; mt < 4; mt++) {
                int m = wm + mt * 16 + gid;
                af[mt][0] = As[m * ASTR + kb + tg];
                af[mt][1] = As[(m + 8) * ASTR + kb + tg];
                af[mt][2] = As[m * ASTR + kb + tg + 4];
                af[mt][3] = As[(m + 8) * ASTR + kb + tg + 4];
            }
            #pragma unroll
            for (int nt = 0; nt < 4; nt++) {
                int n = wn + nt * 8 + gid;
                bf[nt][0] = Bs[(kb + tg) * BSTR + n];
                bf[nt][1] = Bs[(kb + tg + 4) * BSTR + n];
            }
            #pragma unroll
            for (int mt = 0; mt < 4; mt++)
                #pragma unroll
                for (int nt = 0; nt < 4; nt++)
                    mma_tf32(acc[mt][nt], af[mt][0], af[mt][1], af[mt][2], af[mt][3],
                             bf[nt][0], bf[nt][1]);
        }
        __syncthreads();
    }
    #pragma unroll
    for (int mt = 0; mt < 4; mt++) {
        int mA = m0 + wm + mt * 16 + gid, mB = mA + 8;
        #pragma unroll
        for (int nt = 0; nt < 4; nt++) {
            int n = n0 + wn + nt * 8 + tg * 2;
            float v0 = acc[mt][nt][0], v1 = acc[mt][nt][1];
            float v2 = acc[mt][nt][2], v3 = acc[mt][nt][3];
            if (bias) {
                float b0 = bias[n], b1 = bias[n + 1];
                v0 += b0; v1 += b1; v2 += b0; v3 += b1;
            }
            if (resid) {
                v0 += resid[(size_t)mA * N + n];
                v1 += resid[(size_t)mA * N + n + 1];
                v2 += resid[(size_t)mB * N + n];
                v3 += resid[(size_t)mB * N + n + 1];
            }
            C[(size_t)mA * N + n]     = v0;
            C[(size_t)mA * N + n + 1] = v1;
            C[(size_t)mB * N + n]     = v2;
            C[(size_t)mB * N + n + 1] = v3;
        }
    }
}

// ---------------- MoE GEMM1 (tf32): Y1 = gelu(gather(H2) @ W1[e] + b1[e]) ----
__global__ void moe1_tf32(const float* __restrict__ H2,
                          const float* __restrict__ W1,
                          const float* __restrict__ B1,
                          float* __restrict__ Y1) {
    int e = blockIdx.z;
    int cnt = g_cnt[e];
    int m0 = blockIdx.y * 128;
    if (m0 >= cnt) return;
    int off = g_off[e];
    const float* B = W1 + (size_t)e * Dm * FFd;
    const int N = FFd, K = Dm;
    int n0 = blockIdx.x * 128;

    __shared__ unsigned As[128 * ASTR];
    __shared__ unsigned Bs[16 * BSTR];
    __shared__ int toks[128];
    int tid = threadIdx.x;
    int warp = tid >> 5, lane = tid & 31;
    int gid = lane >> 2, tg = lane & 3;
    int wm = (warp >> 2) * 64, wn = (warp & 3) * 32;
    if (tid < 128) {
        int m = m0 + tid;
        toks[tid] = (m < cnt) ? g_sorted[off + m] : -1;
    }
    __syncthreads();

    float acc[4][4][4];
    #pragma unroll
    for (int i = 0; i < 4; i++)
        #pragma unroll
        for (int j = 0; j < 4; j++)
            #pragma unroll
            for (int q = 0; q < 4; q++) acc[i][j][q] = 0.f;

    for (int k0 = 0; k0 < K; k0 += 16) {
        #pragma unroll
        for (int l = 0; l < 2; l++) {
            int idx = tid + l * 256, r = idx >> 2, c4 = (idx & 3) * 4;
            int tok = toks[r];
            float4 v = make_float4(0.f, 0.f, 0.f, 0.f);
            if (tok >= 0)
                v = *(const float4*)(H2 + (size_t)tok * Dm + k0 + c4);
            *(uint4*)&As[r * ASTR + c4] = cvt4(v);
        }
        #pragma unroll
        for (int l = 0; l < 2; l++) {
            int idx = tid + l * 256, r = idx >> 5, c4 = (idx & 31) * 4;
            float4 v = *(const float4*)(B + (size_t)(k0 + r) * N + n0 + c4);
            *(uint4*)&Bs[r * BSTR + c4] = cvt4(v);
        }
        __syncthreads();
        #pragma unroll
        for (int ks = 0; ks < 2; ks++) {
            int kb = ks * 8;
            unsigned af[4][4], bf[4][2];
            #pragma unroll
            for (int mt = 0; mt < 4; mt++) {
                int m = wm + mt * 16 + gid;
                af[mt][0] = As[m * ASTR + kb + tg];
                af[mt][1] = As[(m + 8) * ASTR + kb + tg];
                af[mt][2] = As[m * ASTR + kb + tg + 4];
                af[mt][3] = As[(m + 8) * ASTR + kb + tg + 4];
            }
            #pragma unroll
            for (int nt = 0; nt < 4; nt++) {
                int n = wn + nt * 8 + gid;
                bf[nt][0] = Bs[(kb + tg) * BSTR + n];
                bf[nt][1] = Bs[(kb + tg + 4) * BSTR + n];
            }
            #pragma unroll
            for (int mt = 0; mt < 4; mt++)
                #pragma unroll
                for (int nt = 0; nt < 4; nt++)
                    mma_tf32(acc[mt][nt], af[mt][0], af[mt][1], af[mt][2], af[mt][3],
                             bf[nt][0], bf[nt][1]);
        }
        __syncthreads();
    }
    #pragma unroll
    for (int mt = 0; mt < 4; mt++) {
        int lmA = wm + mt * 16 + gid;
        int gmA = m0 + lmA, gmB = gmA + 8;
        #pragma unroll
        for (int nt = 0; nt < 4; nt++) {
            int n = wn + nt * 8 + tg * 2;
            float b0 = B1[e * FFd + n0 + n], b1 = B1[e * FFd + n0 + n + 1];
            if (gmA < cnt) {
                Y1[(size_t)(off + gmA) * FFd + n0 + n]     = gelu_exact(acc[mt][nt][0] + b0);
                Y1[(size_t)(off + gmA) * FFd + n0 + n + 1] = gelu_exact(acc[mt][nt][1] + b1);
            }
            if (gmB < cnt) {
                Y1[(size_t)(off + gmB) * FFd + n0 + n]     = gelu_exact(acc[mt][nt][2] + b0);
                Y1[(size_t)(off + gmB) * FFd + n0 + n + 1] = gelu_exact(acc[mt][nt][3] + b1);
            }
        }
    }
}

// ---------------- MoE GEMM2 (tf32): out[t] += gelu(Y1 @ W2[e] + b2[e]) ------
__global__ void moe2_tf32(const float* __restrict__ Y1,
                          const float* __restrict__ W2,
                          const float* __restrict__ B2,
                          float* __restrict__ OUT) {
    int e = blockIdx.z;
    int cnt = g_cnt[e];
    int m0 = blockIdx.y * 128;
    if (m0 >= cnt) return;
    int off = g_off[e];
    const float* B = W2 + (size_t)e * FFd * Dm;
    const int N = Dm, K = FFd;
    int n0 = blockIdx.x * 128;

    __shared__ unsigned As[128 * ASTR];
    __shared__ unsigned Bs[16 * BSTR];
    __shared__ int toks[128];
    int tid = threadIdx.x;
    int warp = tid >> 5, lane = tid & 31;
    int gid = lane >> 2, tg = lane & 3;
    int wm = (warp >> 2) * 64, wn = (warp & 3) * 32;
    if (tid < 128) {
        int m = m0 + tid;
        toks[tid] = (m < cnt) ? g_sorted[off + m] : -1;
    }
    __syncthreads();

    float acc[4][4][4];
    #pragma unroll
    for (int i = 0; i < 4; i++)
        #pragma unroll
        for (int j = 0; j < 4; j++)
            #pragma unroll
            for (int q = 0; q < 4; q++) acc[i][j][q] = 0.f;

    for (int k0 = 0; k0 < K; k0 += 16) {
        #pragma unroll
        for (int l = 0; l < 2; l++) {
            int idx = tid + l * 256, r = idx >> 2, c4 = (idx & 3) * 4;
            float4 v = make_float4(0.f, 0.f, 0.f, 0.f);
            if (m0 + r < cnt)
                v = *(const float4*)(Y1 + (size_t)(off + m0 + r) * FFd + k0 + c4);
            *(uint4*)&As[r * ASTR + c4] = cvt4(v);
        }
        #pragma unroll
        for (int l = 0; l < 2; l++) {
            int idx = tid + l * 256, r = idx >> 5, c4 = (idx & 31) * 4;
            float4 v = *(const float4*)(B + (size_t)(k0 + r) * N + n0 + c4);
            *(uint4*)&Bs[r * BSTR + c4] = cvt4(v);
        }
        __syncthreads();
        #pragma unroll
        for (int ks = 0; ks < 2; ks++) {
            int kb = ks * 8;
            unsigned af[4][4], bf[4][2];
            #pragma unroll
            for (int mt = 0; mt < 4; mt++) {
                int m = wm + mt * 16 + gid;
                af[mt][0] = As[m * ASTR + kb + tg];
                af[mt][1] = As[(m + 8) * ASTR + kb + tg];
                af[mt][2] = As[m * ASTR + kb + tg + 4];
                af[mt][3] = As[(m + 8) * ASTR + kb + tg + 4];
            }
            #pragma unroll
            for (int nt = 0; nt < 4; nt++) {
                int n = wn + nt * 8 + gid;
                bf[nt][0] = Bs[(kb + tg) * BSTR + n];
                bf[nt][1] = Bs[(kb + tg + 4) * BSTR + n];
            }
            #pragma unroll
            for (int mt = 0; mt < 4; mt++)
                #pragma unroll
                for (int nt = 0; nt < 4; nt++)
                    mma_tf32(acc[mt][nt], af[mt][0], af[mt][1], af[mt][2], af[mt][3],
                             bf[nt][0], bf[nt][1]);
        }
        __syncthreads();
    }
    #pragma unroll
    for (int mt = 0; mt < 4; mt++) {
        int lmA = wm + mt * 16 + gid;
        int gmA = m0 + lmA, gmB = gmA + 8;
        int tA = toks[lmA], tB = toks[lmA + 8];
        #pragma unroll
        for (int nt = 0; nt < 4; nt++) {
            int n = wn + nt * 8 + tg * 2;
            float b0 = B2[e * Dm + n0 + n], b1 = B2[e * Dm + n0 + n + 1];
            if (gmA < cnt) {
                OUT[(size_t)tA * Dm + n0 + n]     += gelu_exact(acc[mt][nt][0] + b0);
                OUT[(size_t)tA * Dm + n0 + n + 1] += gelu_exact(acc[mt][nt][1] + b1);
            }
            if (gmB < cnt) {
                OUT[(size_t)tB * Dm + n0 + n]     += gelu_exact(acc[mt][nt][2] + b0);
                OUT[(size_t)tB * Dm + n0 + n + 1] += gelu_exact(acc[mt][nt][3] + b1);
            }
        }
    }
}

// ---------------- scores (tf32 mma): S = scale * Q @ K^T --------------------
// 64x64 tile, K=64 all resident. Qs [m][k] str 68, Ks [n][k] str 68.
#define QSTR 68
__global__ void scores_tf32(const float* __restrict__ QKV,
                            float* __restrict__ S) {
    int bh = blockIdx.z;
    int b = bh / Hn, h = bh % Hn;
    int m0 = blockIdx.y * 64, n0 = blockIdx.x * 64;
    __shared__ unsigned Qs[64 * QSTR];
    __shared__ unsigned Ks[64 * QSTR];
    int tid = threadIdx.x;
    int warp = tid >> 5, lane = tid & 31;
    int gid = lane >> 2, tg = lane & 3;
    int wm = (warp >> 2) * 32, wn = (warp & 3) * 16;

    #pragma unroll
    for (int l = 0; l < 4; l++) {
        int idx = tid + l * 256, r = idx >> 4, c4 = (idx & 15) * 4;
        float4 q = *(const float4*)(QKV + (size_t)(b * Sq + m0 + r) * 2304 + h * HDm + c4);
        *(uint4*)&Qs[r * QSTR + c4] = cvt4(q);
        float4 k = *(const float4*)(QKV + (size_t)(b * Sq + n0 + r) * 2304 + Dm + h * HDm + c4);
        *(uint4*)&Ks[r * QSTR + c4] = cvt4(k);
    }
    __syncthreads();

    float acc[2][2][4];
    #pragma unroll
    for (int i = 0; i < 2; i++)
        #pragma unroll
        for (int j = 0; j < 2; j++)
            #pragma unroll
            for (int q = 0; q < 4; q++) acc[i][j][q] = 0.f;

    #pragma unroll
    for (int kb = 0; kb < 64; kb += 8) {
        unsigned af[2][4], bf[2][2];
        #pragma unroll
        for (int mt = 0; mt < 2; mt++) {
            int m = wm + mt * 16 + gid;
            af[mt][0] = Qs[m * QSTR + kb + tg];
            af[mt][1] = Qs[(m + 8) * QSTR + kb + tg];
            af[mt][2] = Qs[m * QSTR + kb + tg + 4];
            af[mt][3] = Qs[(m + 8) * QSTR + kb + tg + 4];
        }
        #pragma unroll
        for (int nt = 0; nt < 2; nt++) {
            int n = wn + nt * 8 + gid;
            bf[nt][0] = Ks[n * QSTR + kb + tg];
            bf[nt][1] = Ks[n * QSTR + kb + tg + 4];
        }
        #pragma unroll
        for (int mt = 0; mt < 2; mt++)
            #pragma unroll
            for (int nt = 0; nt < 2; nt++)
                mma_tf32(acc[mt][nt], af[mt][0], af[mt][1], af[mt][2], af[mt][3],
                         bf[nt][0], bf[nt][1]);
    }

    const float scale = 0.125f;
    #pragma unroll
    for (int mt = 0; mt < 2; mt++) {
        int mA = m0 + wm + mt * 16 + gid, mB = mA + 8;
        #pragma unroll
        for (int nt = 0; nt < 2; nt++) {
            int n = n0 + wn + nt * 8 + tg * 2;
            size_t pA = ((size_t)bh * Sq + mA) * Sq + n;
            size_t pB = ((size_t)bh * Sq + mB) * Sq + n;
            S[pA]     = acc[mt][nt][0] * scale;
            S[pA + 1] = acc[mt][nt][1] * scale;
            S[pB]     = acc[mt][nt][2] * scale;
            S[pB + 1] = acc[mt][nt][3] * scale;
        }
    }
}

// ---------------- row softmax over 512 --------------------------------------
__global__ void softmax_kernel(float* __restrict__ S) {
    size_t row = blockIdx.x;
    int tid = threadIdx.x;
    float* p = S + row * Sq;
    float v0 = p[tid], v1 = p[tid + 256];

    __shared__ float red[256];
    float m = fmaxf(v0, v1);
    red[tid] = m; __syncthreads();
    #pragma unroll
    for (int st = 128; st > 0; st >>= 1) {
        if (tid < st) red[tid] = fmaxf(red[tid], red[tid + st]);
        __syncthreads();
    }
    m = red[0]; __syncthreads();

    float e0 = __expf(v0 - m), e1 = __expf(v1 - m);
    red[tid] = e0 + e1; __syncthreads();
    #pragma unroll
    for (int st = 128; st > 0; st >>= 1) {
        if (tid < st) red[tid] += red[tid + st];
        __syncthreads();
    }
    float inv = 1.0f / red[0];
    p[tid] = e0 * inv;
    p[tid + 256] = e1 * inv;
}

// ---------------- O = P @ V  (tf32 mma) --------------------------------------
// Ps [m][k] str 36 (stage 64x32), Vs [k][n] str 72 (32x64).
#define PSTR 36
#define VSTR 72
__global__ void av_tf32(const float* __restrict__ S,
                        const float* __restrict__ QKV,
                        float* __restrict__ O) {
    int bh = blockIdx.y;
    int b = bh / Hn, h = bh % Hn;
    int m0 = blockIdx.x * 64;
    __shared__ unsigned Ps[64 * PSTR];
    __shared__ unsigned Vs[32 * VSTR];
    int tid = threadIdx.x;
    int warp = tid >> 5, lane = tid & 31;
    int gid = lane >> 2, tg = lane & 3;
    int wm = (warp >> 2) * 32, wn = (warp & 3) * 16;

    float acc[2][2][4];
    #pragma unroll
    for (int i = 0; i < 2; i++)
        #pragma unroll
        for (int j = 0; j < 2; j++)
            #pragma unroll
            for (int q = 0; q < 4; q++) acc[i][j][q] = 0.f;

    for (int k0 = 0; k0 < Sq; k0 += 32) {
        #pragma unroll
        for (int l = 0; l < 2; l++) {
            int idx = tid + l * 256, r = idx >> 3, c4 = (idx & 7) * 4;
            float4 v = *(const float4*)(S + ((size_t)bh * Sq + m0 + r) * Sq + k0 + c4);
            *(uint4*)&Ps[r * PSTR + c4] = cvt4(v);
        }
        #pragma unroll
        for (int l = 0; l < 2; l++) {
            int idx = tid + l * 256, r = idx >> 4, c4 = (idx & 15) * 4;
            float4 v = *(const float4*)(QKV + (size_t)(b * Sq + k0 + r) * 2304 + 2 * Dm + h * HDm + c4);
            *(uint4*)&Vs[r * VSTR + c4] = cvt4(v);
        }
        __syncthreads();
        #pragma unroll
        for (int kb = 0; kb < 32; kb += 8) {
            unsigned af[2][4], bf[2][2];
            #pragma unroll
            for (int mt = 0; mt < 2; mt++) {
                int m = wm + mt * 16 + gid;
                af[mt][0] = Ps[m * PSTR + kb + tg];
                af[mt][1] = Ps[(m + 8) * PSTR + kb + tg];
                af[mt][2] = Ps[m * PSTR + kb + tg + 4];
                af[mt][3] = Ps[(m + 8) * PSTR + kb + tg + 4];
            }
            #pragma unroll
            for (int nt = 0; nt < 2; nt++) {
                int n = wn + nt * 8 + gid;
                bf[nt][0] = Vs[(kb + tg) * VSTR + n];
                bf[nt][1] = Vs[(kb + tg + 4) * VSTR + n];
            }
            #pragma unroll
            for (int mt = 0; mt < 2; mt++)
                #pragma unroll
                for (int nt = 0; nt < 2; nt++)
                    mma_tf32(acc[mt][nt], af[mt][0], af[mt][1], af[mt][2], af[mt][3],
                             bf[nt][0], bf[nt][1]);
        }
        __syncthreads();
    }
    #pragma unroll
    for (int mt = 0; mt < 2; mt++) {
        int mA = m0 + wm + mt * 16 + gid, mB = mA + 8;
        #pragma unroll
        for (int nt = 0; nt < 2; nt++) {
            int n = wn + nt * 8 + tg * 2;
            size_t pA = (size_t)(b * Sq + mA) * Dm + h * HDm + n;
            size_t pB = (size_t)(b * Sq + mB) * Dm + h * HDm + n;
            O[pA]     = acc[mt][nt][0];
            O[pA + 1] = acc[mt][nt][1];
            O[pB]     = acc[mt][nt][2];
            O[pB + 1] = acc[mt][nt][3];
        }
    }
}

// ---------------- router: one warp per token ---------------------------------
__global__ void route_kernel(const float* __restrict__ H2,
                             const float* __restrict__ SW,
                             const float* __restrict__ SB) {
    int warp = (blockIdx.x * blockDim.x + threadIdx.x) >> 5;
    int lane = threadIdx.x & 31;
    if (warp >= TOK) return;
    const float* hrow = H2 + (size_t)warp * Dm;
    float acc[En];
    #pragma unroll
    for (int e = 0; e < En; e++) acc[e] = 0.f;
    for (int d = lane; d < Dm; d += 32) {
        float hv = hrow[d];
        const float* w = SW + d * En;
        #pragma unroll
        for (int e = 0; e < En; e++) acc[e] += hv * w[e];
    }
    #pragma unroll
    for (int e = 0; e < En; e++)
        #pragma unroll
        for (int o = 16; o; o >>= 1)
            acc[e] += __shfl_xor_sync(0xffffffffu, acc[e], o);
    if (lane == 0) {
        float best = acc[0] + SB[0];
        int be = 0;
        #pragma unroll
        for (int e = 1; e < En; e++) {
            float v = acc[e] + SB[e];
            if (v > best) { best = v; be = e; }
        }
        g_routes[warp] = be;
        atomicAdd(&g_cnt[be], 1);
    }
}

__global__ void offsets_kernel() {
    if (threadIdx.x == 0) {
        int acc = 0;
        for (int e = 0; e < En; e++) { g_off[e] = acc; acc += g_cnt[e]; }
    }
}

__global__ void scatter_kernel() {
    int t = blockIdx.x * blockDim.x + threadIdx.x;
    if (t >= TOK) return;
    int e = g_routes[t];
    int pos = atomicAdd(&g_cur[e], 1);
    g_sorted[g_off[e] + pos] = t;
}

// ---------------- launch ------------------------------------------------------
extern "C" void kernel_launch(void* const* d_in, const int* in_sizes, int n_in,
                              void* d_out, int out_size) {
    const float* x       = (const float*)d_in[0];
    // d_in[1] = indexes_list (unused by reference math)
    const float* ln1_g   = (const float*)d_in[2];
    const float* ln1_b   = (const float*)d_in[3];
    const float* qkv_w   = (const float*)d_in[4];
    const float* proj_w  = (const float*)d_in[5];
    const float* proj_b  = (const float*)d_in[6];
    const float* ln2_g   = (const float*)d_in[7];
    const float* ln2_b   = (const float*)d_in[8];
    const float* sw_w    = (const float*)d_in[9];
    const float* sw_b    = (const float*)d_in[10];
    const float* w1      = (const float*)d_in[11];
    const float* b1      = (const float*)d_in[12];
    const float* w2      = (const float*)d_in[13];
    const float* b2      = (const float*)d_in[14];
    float* out = (float*)d_out;

    float *gh, *gqkv, *gs, *go, *gh2, *gy1;
    cudaGetSymbolAddress((void**)&gh,   g_h);
    cudaGetSymbolAddress((void**)&gqkv, g_qkv);
    cudaGetSymbolAddress((void**)&gs,   g_scores);
    cudaGetSymbolAddress((void**)&go,   g_o);
    cudaGetSymbolAddress((void**)&gh2,  g_h2);
    cudaGetSymbolAddress((void**)&gy1,  g_y1);

    reset_kernel<<<1, 32>>>();

    // ln1
    ln_kernel<<<TOK, 256>>>(x, ln1_g, ln1_b, gh);
    // qkv = h @ qkv_w   [4096 x 2304]
    gemm_tf32<<<dim3(2304 / 128, TOK / 128), 256>>>(gh, qkv_w, gqkv,
                                                    TOK, 2304, Dm, nullptr, nullptr);
    // scores
    scores_tf32<<<dim3(Sq / 64, Sq / 64, BHN), 256>>>(gqkv, gs);
    // softmax
    softmax_kernel<<<BHN * Sq, 256>>>(gs);
    // o = P @ V
    av_tf32<<<dim3(Sq / 64, BHN), 256>>>(gs, gqkv, go);
    // xmid = x + o @ proj_w + proj_b   -> written into d_out
    gemm_tf32<<<dim3(Dm / 128, TOK / 128), 256>>>(go, proj_w, out,
                                                  TOK, Dm, Dm, proj_b, x);
    // ln2
    ln_kernel<<<TOK, 256>>>(out, ln2_g, ln2_b, gh2);
    // routing
    route_kernel<<<512, 256>>>(gh2, sw_w, sw_b);
    offsets_kernel<<<1, 32>>>();
    scatter_kernel<<<TOK / 256, 256>>>();
    // MoE expert GEMMs (grouped tokens); extra tiles exit early
    moe1_tf32<<<dim3(FFd / 128, TOK / 128, En), 256>>>(gh2, w1, b1, gy1);
    moe2_tf32<<<dim3(Dm / 128, TOK / 128, En), 256>>>(gy1, w2, b2, out);
}

// round 3
// speedup vs baseline: 2.3622x; 1.0001x over previous
#include <cuda_runtime.h>
#include <math.h>

#define Bsz 8
#define Sq  512
#define Dm  768
#define Hn  12
#define HDm 64
#define En  8
#define FFd 3072
#define TOK 4096
#define BHN 96

// ---------------- scratch (device globals; no allocations allowed) ----------
__device__ float g_h[TOK * Dm];
__device__ float g_qkv[TOK * 3 * Dm];
__device__ float g_scores[(size_t)BHN * Sq * Sq];
__device__ float g_o[TOK * Dm];
__device__ float g_h2[TOK * Dm];
__device__ float g_y1[(size_t)TOK * FFd];
__device__ int   g_routes[TOK];
__device__ int   g_cnt[En];
__device__ int   g_off[En];
__device__ int   g_cur[En];
__device__ int   g_sorted[TOK];

// ---------------- helpers ---------------------------------------------------
__device__ __forceinline__ float gelu_exact(float x) {
    return 0.5f * x * (1.0f + erff(x * 0.70710678118654752f));
}

__device__ __forceinline__ unsigned f2t(float f) {
    unsigned u;
    asm("cvt.rna.tf32.f32 %0, %1;" : "=r"(u) : "f"(f));
    return u;
}
__device__ __forceinline__ uint4 cvt4(float4 v) {
    return make_uint4(f2t(v.x), f2t(v.y), f2t(v.z), f2t(v.w));
}

__device__ __forceinline__ void mma_tf32(float c[4],
                                         unsigned a0, unsigned a1, unsigned a2, unsigned a3,
                                         unsigned b0, unsigned b1) {
    asm volatile(
        "mma.sync.aligned.m16n8k8.row.col.f32.tf32.tf32.f32 "
        "{%0,%1,%2,%3},{%4,%5,%6,%7},{%8,%9},{%0,%1,%2,%3};"
        : "+f"(c[0]), "+f"(c[1]), "+f"(c[2]), "+f"(c[3])
        : "r"(a0), "r"(a1), "r"(a2), "r"(a3), "r"(b0), "r"(b1));
}

// ---------------- reset counters --------------------------------------------
__global__ void reset_kernel() {
    int t = threadIdx.x;
    if (t < En) { g_cnt[t] = 0; g_cur[t] = 0; }
}

// ---------------- layernorm: one block (256 thr) per row of 768 -------------
__global__ void ln_kernel(const float* __restrict__ X,
                          const float* __restrict__ gam,
                          const float* __restrict__ bet,
                          float* __restrict__ Y) {
    int row = blockIdx.x;
    int tid = threadIdx.x;
    const float* x = X + (size_t)row * Dm;
    float v0 = x[tid], v1 = x[tid + 256], v2 = x[tid + 512];

    __shared__ float red[256];
    float s = v0 + v1 + v2;
    red[tid] = s; __syncthreads();
    #pragma unroll
    for (int st = 128; st > 0; st >>= 1) {
        if (tid < st) red[tid] += red[tid + st];
        __syncthreads();
    }
    float mu = red[0] / (float)Dm;
    __syncthreads();

    float d0 = v0 - mu, d1 = v1 - mu, d2 = v2 - mu;
    float q = d0 * d0 + d1 * d1 + d2 * d2;
    red[tid] = q; __syncthreads();
    #pragma unroll
    for (int st = 128; st > 0; st >>= 1) {
        if (tid < st) red[tid] += red[tid + st];
        __syncthreads();
    }
    float rstd = rsqrtf(red[0] / (float)Dm + 1e-5f);

    float* y = Y + (size_t)row * Dm;
    y[tid]       = d0 * rstd * gam[tid]       + bet[tid];
    y[tid + 256] = d1 * rstd * gam[tid + 256] + bet[tid + 256];
    y[tid + 512] = d2 * rstd * gam[tid + 512] + bet[tid + 512];
}

// =============================================================================
// Generic tf32 tensor-core GEMM: C = A@B (+bias)(+resid)
// BM=128, BN=128, BK=16, 256 threads = 8 warps (2x4), warp tile 64x32.
// As: row-major [m][k], stride 20 (20 mod 32 = 20, frag banks 20m+tg distinct).
// Bs: row-major [k][n], stride 136 (mod 32 = 8, frag banks 8k+gid distinct).
// =============================================================================
#define ASTR 20
#define BSTR 136

__global__ void gemm_tf32(const float* __restrict__ A, const float* __restrict__ B,
                          float* __restrict__ C, int M, int N, int K,
                          const float* __restrict__ bias,
                          const float* __restrict__ resid) {
    __shared__ unsigned As[128 * ASTR];
    __shared__ unsigned Bs[16 * BSTR];
    int tid = threadIdx.x;
    int warp = tid >> 5, lane = tid & 31;
    int gid = lane >> 2, tg = lane & 3;
    int wm = (warp >> 2) * 64, wn = (warp & 3) * 32;
    int m0 = blockIdx.y * 128, n0 = blockIdx.x * 128;

    float acc[4][4][4];
    #pragma unroll
    for (int i = 0; i < 4; i++)
        #pragma unroll
        for (int j = 0; j < 4; j++)
            #pragma unroll
            for (int q = 0; q < 4; q++) acc[i][j][q] = 0.f;

    for (int k0 = 0; k0 < K; k0 += 16) {
        #pragma unroll
        for (int l = 0; l < 2; l++) {
            int idx = tid + l * 256, r = idx >> 2, c4 = (idx & 3) * 4;
            float4 v = *(const float4*)(A + (size_t)(m0 + r) * K + k0 + c4);
            *(uint4*)&As[r * ASTR + c4] = cvt4(v);
        }
        #pragma unroll
        for (int l = 0; l < 2; l++) {
            int idx = tid + l * 256, r = idx >> 5, c4 = (idx & 31) * 4;
            float4 v = *(const float4*)(B + (size_t)(k0 + r) * N + n0 + c4);
            *(uint4*)&Bs[r * BSTR + c4] = cvt4(v);
        }
        __syncthreads();
        #pragma unroll
        for (int ks = 0; ks < 2; ks++) {
            int kb = ks * 8;
            unsigned af[4][4], bf[4][2];
            #pragma unroll
            for (int mt = 0; mt < 4; mt++) {
                int m = wm + mt * 16 + gid;
                af[mt][0] = As[m * ASTR + kb + tg];
                af[mt][1] = As[(m + 8) * ASTR + kb + tg];
                af[mt][2] = As[m * ASTR + kb + tg + 4];
                af[mt][3] = As[(m + 8) * ASTR + kb + tg + 4];
            }
            #pragma unroll
            for (int nt = 0; nt < 4; nt++) {
                int n = wn + nt * 8 + gid;
                bf[nt][0] = Bs[(kb + tg) * BSTR + n];
                bf[nt][1] = Bs[(kb + tg + 4) * BSTR + n];
            }
            #pragma unroll
            for (int mt = 0; mt < 4; mt++)
                #pragma unroll
                for (int nt = 0; nt < 4; nt++)
                    mma_tf32(acc[mt][nt], af[mt][0], af[mt][1], af[mt][2], af[mt][3],
                             bf[nt][0], bf[nt][1]);
        }
        __syncthreads();
    }
    #pragma unroll
    for (int mt = 0; mt < 4; mt++) {
        int mA = m0 + wm + mt * 16 + gid, mB = mA + 8;
        #pragma unroll
        for (int nt = 0; nt < 4; nt++) {
            int n = n0 + wn + nt * 8 + tg * 2;
            float v0 = acc[mt][nt][0], v1 = acc[mt][nt][1];
            float v2 = acc[mt][nt][2], v3 = acc[mt][nt][3];
            if (bias) {
                float b0 = bias[n], b1 = bias[n + 1];
                v0 += b0; v1 += b1; v2 += b0; v3 += b1;
            }
            if (resid) {
                v0 += resid[(size_t)mA * N + n];
                v1 += resid[(size_t)mA * N + n + 1];
                v2 += resid[(size_t)mB * N + n];
                v3 += resid[(size_t)mB * N + n + 1];
            }
            C[(size_t)mA * N + n]     = v0;
            C[(size_t)mA * N + n + 1] = v1;
            C[(size_t)mB * N + n]     = v2;
            C[(size_t)mB * N + n + 1] = v3;
        }
    }
}

// ---------------- MoE GEMM1 (tf32): Y1 = gelu(gather(H2) @ W1[e] + b1[e]) ----
__global__ void moe1_tf32(const float* __restrict__ H2,
                          const float* __restrict__ W1,
                          const float* __restrict__ B1,
                          float* __restrict__ Y1) {
    int e = blockIdx.z;
    int cnt = g_cnt[e];
    int m0 = blockIdx.y * 128;
    if (m0 >= cnt) return;
    int off = g_off[e];
    const float* B = W1 + (size_t)e * Dm * FFd;
    const int N = FFd, K = Dm;
    int n0 = blockIdx.x * 128;

    __shared__ unsigned As[128 * ASTR];
    __shared__ unsigned Bs[16 * BSTR];
    __shared__ int toks[128];
    int tid = threadIdx.x;
    int warp = tid >> 5, lane = tid & 31;
    int gid = lane >> 2, tg = lane & 3;
    int wm = (warp >> 2) * 64, wn = (warp & 3) * 32;
    if (tid < 128) {
        int m = m0 + tid;
        toks[tid] = (m < cnt) ? g_sorted[off + m] : -1;
    }
    __syncthreads();

    float acc[4][4][4];
    #pragma unroll
    for (int i = 0; i < 4; i++)
        #pragma unroll
        for (int j = 0; j < 4; j++)
            #pragma unroll
            for (int q = 0; q < 4; q++) acc[i][j][q] = 0.f;

    for (int k0 = 0; k0 < K; k0 += 16) {
        #pragma unroll
        for (int l = 0; l < 2; l++) {
            int idx = tid + l * 256, r = idx >> 2, c4 = (idx & 3) * 4;
            int tok = toks[r];
            float4 v = make_float4(0.f, 0.f, 0.f, 0.f);
            if (tok >= 0)
                v = *(const float4*)(H2 + (size_t)tok * Dm + k0 + c4);
            *(uint4*)&As[r * ASTR + c4] = cvt4(v);
        }
        #pragma unroll
        for (int l = 0; l < 2; l++) {
            int idx = tid + l * 256, r = idx >> 5, c4 = (idx & 31) * 4;
            float4 v = *(const float4*)(B + (size_t)(k0 + r) * N + n0 + c4);
            *(uint4*)&Bs[r * BSTR + c4] = cvt4(v);
        }
        __syncthreads();
        #pragma unroll
        for (int ks = 0; ks < 2; ks++) {
            int kb = ks * 8;
            unsigned af[4][4], bf[4][2];
            #pragma unroll
            for (int mt = 0; mt < 4; mt++) {
                int m = wm + mt * 16 + gid;
                af[mt][0] = As[m * ASTR + kb + tg];
                af[mt][1] = As[(m + 8) * ASTR + kb + tg];
                af[mt][2] = As[m * ASTR + kb + tg + 4];
                af[mt][3] = As[(m + 8) * ASTR + kb + tg + 4];
            }
            #pragma unroll
            for (int nt = 0; nt < 4; nt++) {
                int n = wn + nt * 8 + gid;
                bf[nt][0] = Bs[(kb + tg) * BSTR + n];
                bf[nt][1] = Bs[(kb + tg + 4) * BSTR + n];
            }
            #pragma unroll
            for (int mt = 0; mt < 4; mt++)
                #pragma unroll
                for (int nt = 0; nt < 4; nt++)
                    mma_tf32(acc[mt][nt], af[mt][0], af[mt][1], af[mt][2], af[mt][3],
                             bf[nt][0], bf[nt][1]);
        }
        __syncthreads();
    }
    #pragma unroll
    for (int mt = 0; mt < 4; mt++) {
        int lmA = wm + mt * 16 + gid;
        int gmA = m0 + lmA, gmB = gmA + 8;
        #pragma unroll
        for (int nt = 0; nt < 4; nt++) {
            int n = wn + nt * 8 + tg * 2;
            float b0 = B1[e * FFd + n0 + n], b1 = B1[e * FFd + n0 + n + 1];
            if (gmA < cnt) {
                Y1[(size_t)(off + gmA) * FFd + n0 + n]     = gelu_exact(acc[mt][nt][0] + b0);
                Y1[(size_t)(off + gmA) * FFd + n0 + n + 1] = gelu_exact(acc[mt][nt][1] + b1);
            }
            if (gmB < cnt) {
                Y1[(size_t)(off + gmB) * FFd + n0 + n]     = gelu_exact(acc[mt][nt][2] + b0);
                Y1[(size_t)(off + gmB) * FFd + n0 + n + 1] = gelu_exact(acc[mt][nt][3] + b1);
            }
        }
    }
}

// ---------------- MoE GEMM2 (tf32): out[t] += gelu(Y1 @ W2[e] + b2[e]) ------
__global__ void moe2_tf32(const float* __restrict__ Y1,
                          const float* __restrict__ W2,
                          const float* __restrict__ B2,
                          float* __restrict__ OUT) {
    int e = blockIdx.z;
    int cnt = g_cnt[e];
    int m0 = blockIdx.y * 128;
    if (m0 >= cnt) return;
    int off = g_off[e];
    const float* B = W2 + (size_t)e * FFd * Dm;
    const int N = Dm, K = FFd;
    int n0 = blockIdx.x * 128;

    __shared__ unsigned As[128 * ASTR];
    __shared__ unsigned Bs[16 * BSTR];
    __shared__ int toks[128];
    int tid = threadIdx.x;
    int warp = tid >> 5, lane = tid & 31;
    int gid = lane >> 2, tg = lane & 3;
    int wm = (warp >> 2) * 64, wn = (warp & 3) * 32;
    if (tid < 128) {
        int m = m0 + tid;
        toks[tid] = (m < cnt) ? g_sorted[off + m] : -1;
    }
    __syncthreads();

    float acc[4][4][4];
    #pragma unroll
    for (int i = 0; i < 4; i++)
        #pragma unroll
        for (int j = 0; j < 4; j++)
            #pragma unroll
            for (int q = 0; q < 4; q++) acc[i][j][q] = 0.f;

    for (int k0 = 0; k0 < K; k0 += 16) {
        #pragma unroll
        for (int l = 0; l < 2; l++) {
            int idx = tid + l * 256, r = idx >> 2, c4 = (idx & 3) * 4;
            float4 v = make_float4(0.f, 0.f, 0.f, 0.f);
            if (m0 + r < cnt)
                v = *(const float4*)(Y1 + (size_t)(off + m0 + r) * FFd + k0 + c4);
            *(uint4*)&As[r * ASTR + c4] = cvt4(v);
        }
        #pragma unroll
        for (int l = 0; l < 2; l++) {
            int idx = tid + l * 256, r = idx >> 5, c4 = (idx & 31) * 4;
            float4 v = *(const float4*)(B + (size_t)(k0 + r) * N + n0 + c4);
            *(uint4*)&Bs[r * BSTR + c4] = cvt4(v);
        }
        __syncthreads();
        #pragma unroll
        for (int ks = 0; ks < 2; ks++) {
            int kb = ks * 8;
            unsigned af[4][4], bf[4][2];
            #pragma unroll
            for (int mt = 0; mt < 4; mt++) {
                int m = wm + mt * 16 + gid;
                af[mt][0] = As[m * ASTR + kb + tg];
                af[mt][1] = As[(m + 8) * ASTR + kb + tg];
                af[mt][2] = As[m * ASTR + kb + tg + 4];
                af[mt][3] = As[(m + 8) * ASTR + kb + tg + 4];
            }
            #pragma unroll
            for (int nt = 0; nt < 4; nt++) {
                int n = wn + nt * 8 + gid;
                bf[nt][0] = Bs[(kb + tg) * BSTR + n];
                bf[nt][1] = Bs[(kb + tg + 4) * BSTR + n];
            }
            #pragma unroll
            for (int mt = 0; mt < 4; mt++)
                #pragma unroll
                for (int nt = 0; nt < 4; nt++)
                    mma_tf32(acc[mt][nt], af[mt][0], af[mt][1], af[mt][2], af[mt][3],
                             bf[nt][0], bf[nt][1]);
        }
        __syncthreads();
    }
    #pragma unroll
    for (int mt = 0; mt < 4; mt++) {
        int lmA = wm + mt * 16 + gid;
        int gmA = m0 + lmA, gmB = gmA + 8;
        int tA = toks[lmA], tB = toks[lmA + 8];
        #pragma unroll
        for (int nt = 0; nt < 4; nt++) {
            int n = wn + nt * 8 + tg * 2;
            float b0 = B2[e * Dm + n0 + n], b1 = B2[e * Dm + n0 + n + 1];
            if (gmA < cnt) {
                OUT[(size_t)tA * Dm + n0 + n]     += gelu_exact(acc[mt][nt][0] + b0);
                OUT[(size_t)tA * Dm + n0 + n + 1] += gelu_exact(acc[mt][nt][1] + b1);
            }
            if (gmB < cnt) {
                OUT[(size_t)tB * Dm + n0 + n]     += gelu_exact(acc[mt][nt][2] + b0);
                OUT[(size_t)tB * Dm + n0 + n + 1] += gelu_exact(acc[mt][nt][3] + b1);
            }
        }
    }
}

// ---------------- scores (tf32 mma): S = scale * Q @ K^T --------------------
// 64x64 tile, K=64 all resident. Qs [m][k] str 68, Ks [n][k] str 68.
#define QSTR 68
__global__ void scores_tf32(const float* __restrict__ QKV,
                            float* __restrict__ S) {
    int bh = blockIdx.z;
    int b = bh / Hn, h = bh % Hn;
    int m0 = blockIdx.y * 64, n0 = blockIdx.x * 64;
    __shared__ unsigned Qs[64 * QSTR];
    __shared__ unsigned Ks[64 * QSTR];
    int tid = threadIdx.x;
    int warp = tid >> 5, lane = tid & 31;
    int gid = lane >> 2, tg = lane & 3;
    int wm = (warp >> 2) * 32, wn = (warp & 3) * 16;

    #pragma unroll
    for (int l = 0; l < 4; l++) {
        int idx = tid + l * 256, r = idx >> 4, c4 = (idx & 15) * 4;
        float4 q = *(const float4*)(QKV + (size_t)(b * Sq + m0 + r) * 2304 + h * HDm + c4);
        *(uint4*)&Qs[r * QSTR + c4] = cvt4(q);
        float4 k = *(const float4*)(QKV + (size_t)(b * Sq + n0 + r) * 2304 + Dm + h * HDm + c4);
        *(uint4*)&Ks[r * QSTR + c4] = cvt4(k);
    }
    __syncthreads();

    float acc[2][2][4];
    #pragma unroll
    for (int i = 0; i < 2; i++)
        #pragma unroll
        for (int j = 0; j < 2; j++)
            #pragma unroll
            for (int q = 0; q < 4; q++) acc[i][j][q] = 0.f;

    #pragma unroll
    for (int kb = 0; kb < 64; kb += 8) {
        unsigned af[2][4], bf[2][2];
        #pragma unroll
        for (int mt = 0; mt < 2; mt++) {
            int m = wm + mt * 16 + gid;
            af[mt][0] = Qs[m * QSTR + kb + tg];
            af[mt][1] = Qs[(m + 8) * QSTR + kb + tg];
            af[mt][2] = Qs[m * QSTR + kb + tg + 4];
            af[mt][3] = Qs[(m + 8) * QSTR + kb + tg + 4];
        }
        #pragma unroll
        for (int nt = 0; nt < 2; nt++) {
            int n = wn + nt * 8 + gid;
            bf[nt][0] = Ks[n * QSTR + kb + tg];
            bf[nt][1] = Ks[n * QSTR + kb + tg + 4];
        }
        #pragma unroll
        for (int mt = 0; mt < 2; mt++)
            #pragma unroll
            for (int nt = 0; nt < 2; nt++)
                mma_tf32(acc[mt][nt], af[mt][0], af[mt][1], af[mt][2], af[mt][3],
                         bf[nt][0], bf[nt][1]);
    }

    const float scale = 0.125f;
    #pragma unroll
    for (int mt = 0; mt < 2; mt++) {
        int mA = m0 + wm + mt * 16 + gid, mB = mA + 8;
        #pragma unroll
        for (int nt = 0; nt < 2; nt++) {
            int n = n0 + wn + nt * 8 + tg * 2;
            size_t pA = ((size_t)bh * Sq + mA) * Sq + n;
            size_t pB = ((size_t)bh * Sq + mB) * Sq + n;
            S[pA]     = acc[mt][nt][0] * scale;
            S[pA + 1] = acc[mt][nt][1] * scale;
            S[pB]     = acc[mt][nt][2] * scale;
            S[pB + 1] = acc[mt][nt][3] * scale;
        }
    }
}

// ---------------- row softmax over 512 --------------------------------------
__global__ void softmax_kernel(float* __restrict__ S) {
    size_t row = blockIdx.x;
    int tid = threadIdx.x;
    float* p = S + row * Sq;
    float v0 = p[tid], v1 = p[tid + 256];

    __shared__ float red[256];
    float m = fmaxf(v0, v1);
    red[tid] = m; __syncthreads();
    #pragma unroll
    for (int st = 128; st > 0; st >>= 1) {
        if (tid < st) red[tid] = fmaxf(red[tid], red[tid + st]);
        __syncthreads();
    }
    m = red[0]; __syncthreads();

    float e0 = __expf(v0 - m), e1 = __expf(v1 - m);
    red[tid] = e0 + e1; __syncthreads();
    #pragma unroll
    for (int st = 128; st > 0; st >>= 1) {
        if (tid < st) red[tid] += red[tid + st];
        __syncthreads();
    }
    float inv = 1.0f / red[0];
    p[tid] = e0 * inv;
    p[tid + 256] = e1 * inv;
}

// ---------------- O = P @ V  (tf32 mma) --------------------------------------
// Ps [m][k] str 36 (stage 64x32), Vs [k][n] str 72 (32x64).
#define PSTR 36
#define VSTR 72
__global__ void av_tf32(const float* __restrict__ S,
                        const float* __restrict__ QKV,
                        float* __restrict__ O) {
    int bh = blockIdx.y;
    int b = bh / Hn, h = bh % Hn;
    int m0 = blockIdx.x * 64;
    __shared__ unsigned Ps[64 * PSTR];
    __shared__ unsigned Vs[32 * VSTR];
    int tid = threadIdx.x;
    int warp = tid >> 5, lane = tid & 31;
    int gid = lane >> 2, tg = lane & 3;
    int wm = (warp >> 2) * 32, wn = (warp & 3) * 16;

    float acc[2][2][4];
    #pragma unroll
    for (int i = 0; i < 2; i++)
        #pragma unroll
        for (int j = 0; j < 2; j++)
            #pragma unroll
            for (int q = 0; q < 4; q++) acc[i][j][q] = 0.f;

    for (int k0 = 0; k0 < Sq; k0 += 32) {
        #pragma unroll
        for (int l = 0; l < 2; l++) {
            int idx = tid + l * 256, r = idx >> 3, c4 = (idx & 7) * 4;
            float4 v = *(const float4*)(S + ((size_t)bh * Sq + m0 + r) * Sq + k0 + c4);
            *(uint4*)&Ps[r * PSTR + c4] = cvt4(v);
        }
        #pragma unroll
        for (int l = 0; l < 2; l++) {
            int idx = tid + l * 256, r = idx >> 4, c4 = (idx & 15) * 4;
            float4 v = *(const float4*)(QKV + (size_t)(b * Sq + k0 + r) * 2304 + 2 * Dm + h * HDm + c4);
            *(uint4*)&Vs[r * VSTR + c4] = cvt4(v);
        }
        __syncthreads();
        #pragma unroll
        for (int kb = 0; kb < 32; kb += 8) {
            unsigned af[2][4], bf[2][2];
            #pragma unroll
            for (int mt = 0; mt < 2; mt++) {
                int m = wm + mt * 16 + gid;
                af[mt][0] = Ps[m * PSTR + kb + tg];
                af[mt][1] = Ps[(m + 8) * PSTR + kb + tg];
                af[mt][2] = Ps[m * PSTR + kb + tg + 4];
                af[mt][3] = Ps[(m + 8) * PSTR + kb + tg + 4];
            }
            #pragma unroll
            for (int nt = 0; nt < 2; nt++) {
                int n = wn + nt * 8 + gid;
                bf[nt][0] = Vs[(kb + tg) * VSTR + n];
                bf[nt][1] = Vs[(kb + tg + 4) * VSTR + n];
            }
            #pragma unroll
            for (int mt = 0; mt < 2; mt++)
                #pragma unroll
                for (int nt = 0; nt < 2; nt++)
                    mma_tf32(acc[mt][nt], af[mt][0], af[mt][1], af[mt][2], af[mt][3],
                             bf[nt][0], bf[nt][1]);
        }
        __syncthreads();
    }
    #pragma unroll
    for (int mt = 0; mt < 2; mt++) {
        int mA = m0 + wm + mt * 16 + gid, mB = mA + 8;
        #pragma unroll
        for (int nt = 0; nt < 2; nt++) {
            int n = wn + nt * 8 + tg * 2;
            size_t pA = (size_t)(b * Sq + mA) * Dm + h * HDm + n;
            size_t pB = (size_t)(b * Sq + mB) * Dm + h * HDm + n;
            O[pA]     = acc[mt][nt][0];
            O[pA + 1] = acc[mt][nt][1];
            O[pB]     = acc[mt][nt][2];
            O[pB + 1] = acc[mt][nt][3];
        }
    }
}

// ---------------- router: one warp per token ---------------------------------
__global__ void route_kernel(const float* __restrict__ H2,
                             const float* __restrict__ SW,
                             const float* __restrict__ SB) {
    int warp = (blockIdx.x * blockDim.x + threadIdx.x) >> 5;
    int lane = threadIdx.x & 31;
    if (warp >= TOK) return;
    const float* hrow = H2 + (size_t)warp * Dm;
    float acc[En];
    #pragma unroll
    for (int e = 0; e < En; e++) acc[e] = 0.f;
    for (int d = lane; d < Dm; d += 32) {
        float hv = hrow[d];
        const float* w = SW + d * En;
        #pragma unroll
        for (int e = 0; e < En; e++) acc[e] += hv * w[e];
    }
    #pragma unroll
    for (int e = 0; e < En; e++)
        #pragma unroll
        for (int o = 16; o; o >>= 1)
            acc[e] += __shfl_xor_sync(0xffffffffu, acc[e], o);
    if (lane == 0) {
        float best = acc[0] + SB[0];
        int be = 0;
        #pragma unroll
        for (int e = 1; e < En; e++) {
            float v = acc[e] + SB[e];
            if (v > best) { best = v; be = e; }
        }
        g_routes[warp] = be;
        atomicAdd(&g_cnt[be], 1);
    }
}

__global__ void offsets_kernel() {
    if (threadIdx.x == 0) {
        int acc = 0;
        for (int e = 0; e < En; e++) { g_off[e] = acc; acc += g_cnt[e]; }
    }
}

__global__ void scatter_kernel() {
    int t = blockIdx.x * blockDim.x + threadIdx.x;
    if (t >= TOK) return;
    int e = g_routes[t];
    int pos = atomicAdd(&g_cur[e], 1);
    g_sorted[g_off[e] + pos] = t;
}

// ---------------- launch ------------------------------------------------------
extern "C" void kernel_launch(void* const* d_in, const int* in_sizes, int n_in,
                              void* d_out, int out_size) {
    const float* x       = (const float*)d_in[0];
    // d_in[1] = indexes_list (unused by reference math)
    const float* ln1_g   = (const float*)d_in[2];
    const float* ln1_b   = (const float*)d_in[3];
    const float* qkv_w   = (const float*)d_in[4];
    const float* proj_w  = (const float*)d_in[5];
    const float* proj_b  = (const float*)d_in[6];
    const float* ln2_g   = (const float*)d_in[7];
    const float* ln2_b   = (const float*)d_in[8];
    const float* sw_w    = (const float*)d_in[9];
    const float* sw_b    = (const float*)d_in[10];
    const float* w1      = (const float*)d_in[11];
    const float* b1      = (const float*)d_in[12];
    const float* w2      = (const float*)d_in[13];
    const float* b2      = (const float*)d_in[14];
    float* out = (float*)d_out;

    float *gh, *gqkv, *gs, *go, *gh2, *gy1;
    cudaGetSymbolAddress((void**)&gh,   g_h);
    cudaGetSymbolAddress((void**)&gqkv, g_qkv);
    cudaGetSymbolAddress((void**)&gs,   g_scores);
    cudaGetSymbolAddress((void**)&go,   g_o);
    cudaGetSymbolAddress((void**)&gh2,  g_h2);
    cudaGetSymbolAddress((void**)&gy1,  g_y1);

    reset_kernel<<<1, 32>>>();

    // ln1
    ln_kernel<<<TOK, 256>>>(x, ln1_g, ln1_b, gh);
    // qkv = h @ qkv_w   [4096 x 2304]
    gemm_tf32<<<dim3(2304 / 128, TOK / 128), 256>>>(gh, qkv_w, gqkv,
                                                    TOK, 2304, Dm, nullptr, nullptr);
    // scores
    scores_tf32<<<dim3(Sq / 64, Sq / 64, BHN), 256>>>(gqkv, gs);
    // softmax
    softmax_kernel<<<BHN * Sq, 256>>>(gs);
    // o = P @ V
    av_tf32<<<dim3(Sq / 64, BHN), 256>>>(gs, gqkv, go);
    // xmid = x + o @ proj_w + proj_b   -> written into d_out
    gemm_tf32<<<dim3(Dm / 128, TOK / 128), 256>>>(go, proj_w, out,
                                                  TOK, Dm, Dm, proj_b, x);
    // ln2
    ln_kernel<<<TOK, 256>>>(out, ln2_g, ln2_b, gh2);
    // routing
    route_kernel<<<512, 256>>>(gh2, sw_w, sw_b);
    offsets_kernel<<<1, 32>>>();
    scatter_kernel<<<TOK / 256, 256>>>();
    // MoE expert GEMMs (grouped tokens); extra tiles exit early
    moe1_tf32<<<dim3(FFd / 128, TOK / 128, En), 256>>>(gh2, w1, b1, gy1);
    moe2_tf32<<<dim3(Dm / 128, TOK / 128, En), 256>>>(gy1, w2, b2, out);
}